// round 1
// baseline (speedup 1.0000x reference)
#include <cuda_runtime.h>
#include <cuda_bf16.h>

// Problem: B=4 batches. For each query point, find nearest anchor (argmin of
// expanded squared distance, first-index tie-break), then count queries where
// diff . (summed face normal of nn) < 0 and |diff| <= 5.
// Key simplification: vertex-normal normalization and /(cnt+eps) are positive
// scalings -> sign of dot is unchanged -> use raw atomic-summed face normals.

#define BATCHES 4
#define MAXNA   8192
#define TILE    1024
#define NN_BLOCK 128

__device__ float4 g_W[BATCHES * MAXNA];          // (-2ax, -2ay, -2az, a2)
__device__ float  g_acc[BATCHES * MAXNA * 3];    // summed face normals

// ---------------------------------------------------------------------------
// Kernel 0: zero output + accumulators, precompute anchor weights
// ---------------------------------------------------------------------------
__global__ void prep_kernel(const float* __restrict__ anchor, float* __restrict__ out,
                            int Na)
{
    int i = blockIdx.x * blockDim.x + threadIdx.x;
    if (i < BATCHES) out[i] = 0.0f;
    int tot = BATCHES * Na;
    if (i < tot) {
        const float* p = anchor + (size_t)i * 3;
        float x = p[0], y = p[1], z = p[2];
        g_W[i] = make_float4(-2.0f * x, -2.0f * y, -2.0f * z,
                             x * x + y * y + z * z);
        float* acc = g_acc + (size_t)i * 3;
        acc[0] = 0.0f; acc[1] = 0.0f; acc[2] = 0.0f;
    }
}

// ---------------------------------------------------------------------------
// Kernel 1: face normals scatter-add (cross(v1-v0, v2-v0) into 3 vertices)
// ---------------------------------------------------------------------------
__global__ void face_kernel(const float* __restrict__ anchor,
                            const int* __restrict__ faces,
                            int Na, int F)
{
    int i = blockIdx.x * blockDim.x + threadIdx.x;
    if (i >= BATCHES * F) return;
    int b = i / F;
    int f = i - b * F;

    int i0 = faces[3 * f + 0];
    int i1 = faces[3 * f + 1];
    int i2 = faces[3 * f + 2];

    const float* base = anchor + (size_t)b * Na * 3;
    float v0x = base[3 * i0 + 0], v0y = base[3 * i0 + 1], v0z = base[3 * i0 + 2];
    float v1x = base[3 * i1 + 0], v1y = base[3 * i1 + 1], v1z = base[3 * i1 + 2];
    float v2x = base[3 * i2 + 0], v2y = base[3 * i2 + 1], v2z = base[3 * i2 + 2];

    float e1x = v1x - v0x, e1y = v1y - v0y, e1z = v1z - v0z;
    float e2x = v2x - v0x, e2y = v2y - v0y, e2z = v2z - v0z;

    float nx = e1y * e2z - e1z * e2y;
    float ny = e1z * e2x - e1x * e2z;
    float nz = e1x * e2y - e1y * e2x;

    float* acc = g_acc + (size_t)b * Na * 3;
    atomicAdd(&acc[3 * i0 + 0], nx);
    atomicAdd(&acc[3 * i0 + 1], ny);
    atomicAdd(&acc[3 * i0 + 2], nz);
    atomicAdd(&acc[3 * i1 + 0], nx);
    atomicAdd(&acc[3 * i1 + 1], ny);
    atomicAdd(&acc[3 * i1 + 2], nz);
    atomicAdd(&acc[3 * i2 + 0], nx);
    atomicAdd(&acc[3 * i2 + 1], ny);
    atomicAdd(&acc[3 * i2 + 2], nz);
}

// ---------------------------------------------------------------------------
// Kernel 2: brute-force NN (one thread per query) + collision count
// d' = a2 - 2*q.a  (q2 constant per query -> same argmin as reference's
// q2 + a2 - 2*dot; strict '<' keeps the first index on ties like jnp.argmin)
// ---------------------------------------------------------------------------
__global__ void __launch_bounds__(NN_BLOCK)
nn_kernel(const float* __restrict__ query,
          const float* __restrict__ anchor,
          float* __restrict__ out,
          int Nq, int Na)
{
    __shared__ float4 sW[TILE];

    int b = blockIdx.y;
    int q = blockIdx.x * NN_BLOCK + threadIdx.x;
    bool valid = (q < Nq);
    int qc = valid ? q : 0;

    const float* qp = query + ((size_t)b * Nq + qc) * 3;
    float qx = qp[0], qy = qp[1], qz = qp[2];

    const float4* W = g_W + (size_t)b * Na;

    float dmin = 3.402823466e38f;
    int best = 0;

    for (int base = 0; base < Na; base += TILE) {
        int n = Na - base;
        if (n > TILE) n = TILE;
        for (int i = threadIdx.x; i < n; i += NN_BLOCK)
            sW[i] = W[base + i];
        __syncthreads();

        int a = 0;
        for (; a + 8 <= n; a += 8) {
            #pragma unroll
            for (int u = 0; u < 8; u++) {
                float4 w = sW[a + u];
                float d = fmaf(w.x, qx, fmaf(w.y, qy, fmaf(w.z, qz, w.w)));
                if (d < dmin) { dmin = d; best = base + a + u; }
            }
        }
        for (; a < n; a++) {
            float4 w = sW[a];
            float d = fmaf(w.x, qx, fmaf(w.y, qy, fmaf(w.z, qz, w.w)));
            if (d < dmin) { dmin = d; best = base + a; }
        }
        __syncthreads();
    }

    // gather nearest anchor + raw normal, evaluate collision predicate
    const float* ap = anchor + ((size_t)b * Na + best) * 3;
    float dx = qx - ap[0];
    float dy = qy - ap[1];
    float dz = qz - ap[2];

    const float* np = g_acc + ((size_t)b * Na + best) * 3;
    float dot = dx * np[0] + dy * np[1] + dz * np[2];
    float l2  = sqrtf(dx * dx + dy * dy + dz * dz);

    int coll = (valid && (l2 <= 5.0f) && (dot < 0.0f)) ? 1 : 0;

    unsigned m = __ballot_sync(0xFFFFFFFFu, coll);
    if ((threadIdx.x & 31) == 0 && m)
        atomicAdd(&out[b], (float)__popc(m));
}

// ---------------------------------------------------------------------------
extern "C" void kernel_launch(void* const* d_in, const int* in_sizes, int n_in,
                              void* d_out, int out_size)
{
    const float* query  = (const float*)d_in[0];
    const float* anchor = (const float*)d_in[1];
    const int*   faces  = (const int*)d_in[2];
    float* out = (float*)d_out;

    const int B  = BATCHES;
    int Nq = in_sizes[0] / (B * 3);
    int Na = in_sizes[1] / (B * 3);
    int F  = in_sizes[2] / 3;

    int prep_threads = B * Na;
    prep_kernel<<<(prep_threads + 255) / 256, 256>>>(anchor, out, Na);

    face_kernel<<<(B * F + 255) / 256, 256>>>(anchor, faces, Na, F);

    dim3 grid((Nq + NN_BLOCK - 1) / NN_BLOCK, B);
    nn_kernel<<<grid, NN_BLOCK>>>(query, anchor, out, Nq, Na);
}

// round 3
// speedup vs baseline: 1.2404x; 1.2404x over previous
#include <cuda_runtime.h>
#include <cuda_bf16.h>
#include <float.h>

// B=4 batches. Per query: argmin over anchors of d' = a2 - 2*q.a (same argmin
// as squared distance; strict first-index tie-break), then count dot(diff,
// summed face normal) < 0 within MAX_DIST. Normal normalization is a positive
// scaling -> sign unchanged -> raw atomic-summed face normals suffice.
//
// NN inner loop: packed fp32x2 FMA (2 anchors / issue slot), index-free fminf
// accumulation, per-32-anchor-chunk winner tracking, exact rescan of the
// winning chunk with bit-identical scalar FMA chains.

#define BATCHES 4
#define MAXA    8192
#define MAXP    (MAXA / 2)
#define TILE_A  1024
#define TILE_P  (TILE_A / 2)

typedef unsigned long long u64;

__device__ float4 g_WA[BATCHES * MAXP];  // (wx0, wx1, wy0, wy1), w = -2*a
__device__ float4 g_WB[BATCHES * MAXP];  // (wz0, wz1, ww0, ww1), ww = a2
__device__ float  g_acc[BATCHES * MAXA * 3];

__device__ __forceinline__ u64 fma2(u64 a, u64 b, u64 c) {
    u64 r;
    asm("fma.rn.f32x2 %0,%1,%2,%3;" : "=l"(r) : "l"(a), "l"(b), "l"(c));
    return r;
}
__device__ __forceinline__ u64 bcast2(float x) {
    u64 r;
    asm("mov.b64 %0,{%1,%1};" : "=l"(r) : "f"(x));
    return r;
}
__device__ __forceinline__ float lo2(u64 v) {
    float r;
    asm("{ .reg .f32 t; mov.b64 {%0, t}, %1; }" : "=f"(r) : "l"(v));
    return r;
}
__device__ __forceinline__ float hi2(u64 v) {
    float r;
    asm("{ .reg .f32 t; mov.b64 {t, %0}, %1; }" : "=f"(r) : "l"(v));
    return r;
}

// ---------------------------------------------------------------------------
// Kernel 0: zero output + accumulators, build pair-SoA anchor weights
// ---------------------------------------------------------------------------
__global__ void prep_kernel(const float* __restrict__ anchor,
                            float* __restrict__ out, int Na, int NaPad)
{
    int i = blockIdx.x * blockDim.x + threadIdx.x;
    if (i < BATCHES) out[i] = 0.0f;

    int pairsPad = NaPad >> 1;
    if (i < BATCHES * pairsPad) {
        int b = i / pairsPad;
        int p = i - b * pairsPad;
        int a0 = 2 * p, a1 = 2 * p + 1;
        float4 A, Bv;
        if (a0 < Na) {
            const float* s = anchor + ((size_t)b * Na + a0) * 3;
            float x = s[0], y = s[1], z = s[2];
            A.x = -2.0f * x; A.z = -2.0f * y; Bv.x = -2.0f * z;
            Bv.z = x * x + y * y + z * z;
        } else { A.x = 0.0f; A.z = 0.0f; Bv.x = 0.0f; Bv.z = FLT_MAX; }
        if (a1 < Na) {
            const float* s = anchor + ((size_t)b * Na + a1) * 3;
            float x = s[0], y = s[1], z = s[2];
            A.y = -2.0f * x; A.w = -2.0f * y; Bv.y = -2.0f * z;
            Bv.w = x * x + y * y + z * z;
        } else { A.y = 0.0f; A.w = 0.0f; Bv.y = 0.0f; Bv.w = FLT_MAX; }
        g_WA[i] = A;
        g_WB[i] = Bv;
    }

    if (i < BATCHES * Na * 3) g_acc[i] = 0.0f;
}

// ---------------------------------------------------------------------------
// Kernel 1: face normals scatter-add
// ---------------------------------------------------------------------------
__global__ void face_kernel(const float* __restrict__ anchor,
                            const int* __restrict__ faces, int Na, int F)
{
    int i = blockIdx.x * blockDim.x + threadIdx.x;
    if (i >= BATCHES * F) return;
    int b = i / F;
    int f = i - b * F;

    int i0 = faces[3 * f + 0];
    int i1 = faces[3 * f + 1];
    int i2 = faces[3 * f + 2];

    const float* base = anchor + (size_t)b * Na * 3;
    float v0x = base[3 * i0 + 0], v0y = base[3 * i0 + 1], v0z = base[3 * i0 + 2];
    float v1x = base[3 * i1 + 0], v1y = base[3 * i1 + 1], v1z = base[3 * i1 + 2];
    float v2x = base[3 * i2 + 0], v2y = base[3 * i2 + 1], v2z = base[3 * i2 + 2];

    float e1x = v1x - v0x, e1y = v1y - v0y, e1z = v1z - v0z;
    float e2x = v2x - v0x, e2y = v2y - v0y, e2z = v2z - v0z;

    float nx = e1y * e2z - e1z * e2y;
    float ny = e1z * e2x - e1x * e2z;
    float nz = e1x * e2y - e1y * e2x;

    float* acc = g_acc + (size_t)b * Na * 3;
    atomicAdd(&acc[3 * i0 + 0], nx);
    atomicAdd(&acc[3 * i0 + 1], ny);
    atomicAdd(&acc[3 * i0 + 2], nz);
    atomicAdd(&acc[3 * i1 + 0], nx);
    atomicAdd(&acc[3 * i1 + 1], ny);
    atomicAdd(&acc[3 * i1 + 2], nz);
    atomicAdd(&acc[3 * i2 + 0], nx);
    atomicAdd(&acc[3 * i2 + 1], ny);
    atomicAdd(&acc[3 * i2 + 2], nz);
}

// ---------------------------------------------------------------------------
// Kernel 2: brute-force NN + collision count. One warp per CTA.
// ---------------------------------------------------------------------------
__global__ void __launch_bounds__(32)
nn_kernel(const float* __restrict__ query,
          const float* __restrict__ anchor,
          float* __restrict__ out,
          int Nq, int Na, int NaPad)
{
    __shared__ float4 sA[TILE_P];
    __shared__ float4 sB[TILE_P];

    int b = blockIdx.y;
    int q = blockIdx.x * 32 + threadIdx.x;
    bool valid = (q < Nq);
    int qc = valid ? q : 0;

    const float* qp = query + ((size_t)b * Nq + qc) * 3;
    float qx = qp[0], qy = qp[1], qz = qp[2];
    u64 qx2 = bcast2(qx), qy2 = bcast2(qy), qz2 = bcast2(qz);

    int pairsPad = NaPad >> 1;
    const float4* WA = g_WA + (size_t)b * pairsPad;
    const float4* WB = g_WB + (size_t)b * pairsPad;

    float gmin = FLT_MAX;
    int gbase = 0;

    for (int base = 0; base < NaPad; base += TILE_A) {
        int nA = NaPad - base; if (nA > TILE_A) nA = TILE_A;
        int nP = nA >> 1;
        int p0 = base >> 1;
        for (int i = threadIdx.x; i < nP; i += 32) {
            sA[i] = WA[p0 + i];
            sB[i] = WB[p0 + i];
        }
        __syncwarp();

        for (int c = 0; c < nA; c += 32) {          // chunk = 32 anchors
            int cp = c >> 1;                         // 16 pairs
            float m0 = FLT_MAX, m1 = FLT_MAX, m2 = FLT_MAX, m3 = FLT_MAX;
            #pragma unroll
            for (int j = 0; j < 16; j += 2) {
                ulonglong2 A0 = *(const ulonglong2*)&sA[cp + j];
                ulonglong2 B0 = *(const ulonglong2*)&sB[cp + j];
                ulonglong2 A1 = *(const ulonglong2*)&sA[cp + j + 1];
                ulonglong2 B1 = *(const ulonglong2*)&sB[cp + j + 1];
                u64 t0 = fma2(A0.x, qx2, fma2(A0.y, qy2, fma2(B0.x, qz2, B0.y)));
                u64 t1 = fma2(A1.x, qx2, fma2(A1.y, qy2, fma2(B1.x, qz2, B1.y)));
                m0 = fminf(m0, lo2(t0));
                m1 = fminf(m1, hi2(t0));
                m2 = fminf(m2, lo2(t1));
                m3 = fminf(m3, hi2(t1));
            }
            float cm = fminf(fminf(m0, m1), fminf(m2, m3));
            if (cm < gmin) { gmin = cm; gbase = base + c; }
        }
        __syncwarp();
    }

    // Exact rescan of the winning 32-anchor chunk (bit-identical FMA chains)
    int best = gbase;
    {
        int pr = gbase >> 1;
        bool found = false;
        #pragma unroll 1
        for (int j = 0; j < 16 && !found; j++) {
            float4 A  = WA[pr + j];
            float4 Bv = WB[pr + j];
            float d0 = fmaf(A.x, qx, fmaf(A.z, qy, fmaf(Bv.x, qz, Bv.z)));
            float d1 = fmaf(A.y, qx, fmaf(A.w, qy, fmaf(Bv.y, qz, Bv.w)));
            if (d0 == gmin)      { best = gbase + 2 * j;     found = true; }
            else if (d1 == gmin) { best = gbase + 2 * j + 1; found = true; }
        }
    }

    // Gather nearest anchor + raw normal, evaluate predicate
    const float* ap = anchor + ((size_t)b * Na + best) * 3;
    float dx = qx - ap[0];
    float dy = qy - ap[1];
    float dz = qz - ap[2];

    const float* npx = g_acc + ((size_t)b * Na + best) * 3;
    float dot = dx * npx[0] + dy * npx[1] + dz * npx[2];
    float l2  = sqrtf(dx * dx + dy * dy + dz * dz);

    int coll = (valid && (l2 <= 5.0f) && (dot < 0.0f)) ? 1 : 0;
    unsigned m = __ballot_sync(0xFFFFFFFFu, coll);
    if (threadIdx.x == 0 && m)
        atomicAdd(&out[b], (float)__popc(m));
}

// ---------------------------------------------------------------------------
extern "C" void kernel_launch(void* const* d_in, const int* in_sizes, int n_in,
                              void* d_out, int out_size)
{
    const float* query  = (const float*)d_in[0];
    const float* anchor = (const float*)d_in[1];
    const int*   faces  = (const int*)d_in[2];
    float* out = (float*)d_out;

    const int B = BATCHES;
    int Nq = in_sizes[0] / (B * 3);
    int Na = in_sizes[1] / (B * 3);
    int F  = in_sizes[2] / 3;
    int NaPad = ((Na + 31) / 32) * 32;

    int prep_n = B * Na * 3;
    int prep_n2 = B * (NaPad >> 1);
    if (prep_n2 > prep_n) prep_n = prep_n2;
    prep_kernel<<<(prep_n + 255) / 256, 256>>>(anchor, out, Na, NaPad);

    face_kernel<<<(B * F + 255) / 256, 256>>>(anchor, faces, Na, F);

    dim3 grid((Nq + 31) / 32, B);
    nn_kernel<<<grid, 32>>>(query, anchor, out, Nq, Na, NaPad);
}